// round 9
// baseline (speedup 1.0000x reference)
#include <cuda_runtime.h>
#include <cuda_fp16.h>
#include <mma.h>

using namespace nvcuda;

#define Mv    32768
#define Ev    262144
#define RANKv 5
#define FILTv 32
#define FINv  32
#define NBv   8
#define VEC   256   // FIN * NB

typedef unsigned long long u64;
typedef unsigned int u32;

struct alignas(8) Edge { int c; float w; };

// T terms fp16 (rank 4 never materialized), element layout per vertex: idx = n*32 + f
__device__ __half g_T[4][(size_t)Mv * VEC];
__device__ int   g_cnt[Mv];          // zero at module load; re-zeroed by k_scan each replay
__device__ int   g_rowptr[Mv + 1];
__device__ int   g_pos[Ev];
__device__ Edge  g_edge[Ev];

// ---------------- CSR build ----------------
__global__ void k_hist(const int* __restrict__ rows) {
    int e = blockIdx.x * 256 + threadIdx.x;
    g_pos[e] = atomicAdd(&g_cnt[rows[e]], 1);
}

// scan g_cnt -> g_rowptr, then zero g_cnt (restores invariant for next replay)
__global__ void k_scan() {
    __shared__ int part[1024];
    int t = threadIdx.x;
    int base = t * 32;
    int s = 0;
#pragma unroll
    for (int i = 0; i < 32; i++) s += g_cnt[base + i];
    part[t] = s;
    __syncthreads();
    for (int off = 1; off < 1024; off <<= 1) {
        int v = (t >= off) ? part[t - off] : 0;
        __syncthreads();
        part[t] += v;
        __syncthreads();
    }
    int excl = (t == 0) ? 0 : part[t - 1];
#pragma unroll
    for (int i = 0; i < 32; i++) {
        g_rowptr[base + i] = excl;
        excl += g_cnt[base + i];
    }
    if (t == 1023) g_rowptr[Mv] = Ev;
#pragma unroll
    for (int i = 0; i < 32; i++) g_cnt[base + i] = 0;
}

// fused: blocks [0,1024) build edge array; blocks [1024,5120) transpose x -> T0 fp16
__global__ void __launch_bounds__(256) k_scatter_init(const int* __restrict__ rows,
                                                      const int* __restrict__ cols,
                                                      const float* __restrict__ vals,
                                                      const float* __restrict__ x) {
    int t = threadIdx.x;
    if (blockIdx.x < 1024) {
        int e = blockIdx.x * 256 + t;
        int idx = g_rowptr[rows[e]] + g_pos[e];
        Edge ed; ed.c = cols[e] * VEC; ed.w = vals[e];
        g_edge[idx] = ed;
    } else {
        int b = blockIdx.x - 1024;
        int m = b * 8 + (t >> 5);
        int l = t & 31;
        int n = l >> 2;            // element block 8l..8l+7 = n*32 + f0..f0+7
        int f0 = 8 * (l & 3);
        const float* xp = &x[((size_t)n * Mv + m) * FINv + f0];
        float4 va = *(const float4*)xp;
        float4 vb = *(const float4*)(xp + 4);
        uint4 u;
        __half2 h;
        h = __floats2half2_rn(va.x, va.y); u.x = *(u32*)&h;
        h = __floats2half2_rn(va.z, va.w); u.y = *(u32*)&h;
        h = __floats2half2_rn(vb.x, vb.y); u.z = *(u32*)&h;
        h = __floats2half2_rn(vb.z, vb.w); u.w = *(u32*)&h;
        *(uint4*)&g_T[0][(size_t)m * VEC + 8 * l] = u;
    }
}

// ---------------- Chebyshev step: one warp per row, fp16 in/out, fp32 accum ----------------
__global__ void __launch_bounds__(256) k_step(int prevIdx, int ppIdx, int curIdx, int isFirst) {
    int t = threadIdx.x;
    int w = t >> 5, l = t & 31;
    int m = blockIdx.x * 8 + w;

    const __half* __restrict__ Tprev = g_T[prevIdx];
    const __half* __restrict__ Tpp   = g_T[ppIdx];
    __half* __restrict__ Tcur        = g_T[curIdx];

    size_t base = (size_t)m * VEC + 8 * l;
    uint4 ppu = make_uint4(0, 0, 0, 0);
    if (!isFirst) ppu = *(const uint4*)&Tpp[base];

    int s = __ldg(&g_rowptr[m]), e = __ldg(&g_rowptr[m + 1]);
    float2 a0 = {0.f,0.f}, a1 = {0.f,0.f}, a2 = {0.f,0.f}, a3 = {0.f,0.f};
    for (int i = s; i < e; i++) {
        Edge ed = g_edge[i];
        uint4 v = *(const uint4*)&Tprev[(size_t)ed.c + 8 * l];
        float wv = ed.w;
        float2 f0 = __half22float2(*(__half2*)&v.x);
        float2 f1 = __half22float2(*(__half2*)&v.y);
        float2 f2v = __half22float2(*(__half2*)&v.z);
        float2 f3 = __half22float2(*(__half2*)&v.w);
        a0.x += wv * f0.x;  a0.y += wv * f0.y;
        a1.x += wv * f1.x;  a1.y += wv * f1.y;
        a2.x += wv * f2v.x; a2.y += wv * f2v.y;
        a3.x += wv * f3.x;  a3.y += wv * f3.y;
    }

    if (!isFirst) {
        float2 p0 = __half22float2(*(__half2*)&ppu.x);
        float2 p1 = __half22float2(*(__half2*)&ppu.y);
        float2 p2 = __half22float2(*(__half2*)&ppu.z);
        float2 p3 = __half22float2(*(__half2*)&ppu.w);
        a0.x = 2.f * a0.x - p0.x;  a0.y = 2.f * a0.y - p0.y;
        a1.x = 2.f * a1.x - p1.x;  a1.y = 2.f * a1.y - p1.y;
        a2.x = 2.f * a2.x - p2.x;  a2.y = 2.f * a2.y - p2.y;
        a3.x = 2.f * a3.x - p3.x;  a3.y = 2.f * a3.y - p3.y;
    }

    uint4 u;
    __half2 h;
    h = __floats2half2_rn(a0.x, a0.y); u.x = *(u32*)&h;
    h = __floats2half2_rn(a1.x, a1.y); u.y = *(u32*)&h;
    h = __floats2half2_rn(a2.x, a2.y); u.z = *(u32*)&h;
    h = __floats2half2_rn(a3.x, a3.y); u.w = *(u32*)&h;
    *(uint4*)&Tcur[base] = u;
}

// ---------------- fused last step + tensor-core GEMM ----------------
// T4 = 2 L T3 - T2 computed in regs; A tile = [tr=n*8+m_local][kr*32+f] fp16;
// out[(n*Mv+m)*32+filt] = bias + A @ W_fp16.
#define A_LD 168   // 160 + 8 halfs pad

__global__ void __launch_bounds__(256) k_step_fin(const float* __restrict__ kern,
                                                  const float* __restrict__ bias,
                                                  float* __restrict__ out) {
    __shared__ alignas(16) __half smA[64 * A_LD];   // 21504 B
    __shared__ alignas(16) __half smB[160 * FILTv]; // 10240 B
    __shared__ float  smBias[16 * FILTv];           //  2048 B
    __shared__ float  smC[64 * FILTv];              //  8192 B

    int t = threadIdx.x;
    int w = t >> 5, l = t & 31;
    int m0 = blockIdx.x * 8;
    int m = m0 + w;
    int n = l >> 2, f0 = 8 * (l & 3);
    int tr = n * 8 + w;

    // stage T0..T3 rows of A (issued early; overlaps with gather below)
#pragma unroll
    for (int kr = 0; kr < 4; kr++) {
        uint4 v = *(const uint4*)&g_T[kr][(size_t)m * VEC + 8 * l];
        *(uint4*)&smA[tr * A_LD + kr * 32 + f0] = v;
    }

    // B: W fp32 -> fp16, rows reordered to (kr*32+f)
    for (int i = t; i < 160 * FILTv; i += 256) {
        int row = i >> 5, filt = i & 31;
        int kr = row >> 5, f = row & 31;
        smB[i] = __float2half_rn(kern[(f * RANKv + kr) * FILTv + filt]);
    }
    for (int i = t; i < 16 * FILTv; i += 256)
        smBias[i] = bias[i & 31];

    // gather T4 = 2 L T3 - T2 for row m
    {
        const __half* __restrict__ Tprev = g_T[3];
        const __half* __restrict__ Tpp   = g_T[2];
        uint4 ppu = *(const uint4*)&Tpp[(size_t)m * VEC + 8 * l];

        int s = __ldg(&g_rowptr[m]), e = __ldg(&g_rowptr[m + 1]);
        float2 a0 = {0.f,0.f}, a1 = {0.f,0.f}, a2 = {0.f,0.f}, a3 = {0.f,0.f};
        for (int i = s; i < e; i++) {
            Edge ed = g_edge[i];
            uint4 v = *(const uint4*)&Tprev[(size_t)ed.c + 8 * l];
            float wv = ed.w;
            float2 q0 = __half22float2(*(__half2*)&v.x);
            float2 q1 = __half22float2(*(__half2*)&v.y);
            float2 q2 = __half22float2(*(__half2*)&v.z);
            float2 q3 = __half22float2(*(__half2*)&v.w);
            a0.x += wv * q0.x; a0.y += wv * q0.y;
            a1.x += wv * q1.x; a1.y += wv * q1.y;
            a2.x += wv * q2.x; a2.y += wv * q2.y;
            a3.x += wv * q3.x; a3.y += wv * q3.y;
        }
        float2 p0 = __half22float2(*(__half2*)&ppu.x);
        float2 p1 = __half22float2(*(__half2*)&ppu.y);
        float2 p2 = __half22float2(*(__half2*)&ppu.z);
        float2 p3 = __half22float2(*(__half2*)&ppu.w);
        uint4 u;
        __half2 h;
        h = __floats2half2_rn(2.f*a0.x - p0.x, 2.f*a0.y - p0.y); u.x = *(u32*)&h;
        h = __floats2half2_rn(2.f*a1.x - p1.x, 2.f*a1.y - p1.y); u.y = *(u32*)&h;
        h = __floats2half2_rn(2.f*a2.x - p2.x, 2.f*a2.y - p2.y); u.z = *(u32*)&h;
        h = __floats2half2_rn(2.f*a3.x - p3.x, 2.f*a3.y - p3.y); u.w = *(u32*)&h;
        *(uint4*)&smA[tr * A_LD + 4 * 32 + f0] = u;
    }
    __syncthreads();

    // wmma: 8 warps -> 8 tiles: row-tile wr = w>>1 (rows 16wr..16wr+15), col-tile wc = w&1
    {
        int wr = w >> 1, wc = w & 1;
        wmma::fragment<wmma::accumulator, 16, 16, 16, float> acc;
        wmma::load_matrix_sync(acc, smBias + wc * 16, FILTv, wmma::mem_row_major);
#pragma unroll
        for (int kk = 0; kk < 10; kk++) {
            wmma::fragment<wmma::matrix_a, 16, 16, 16, __half, wmma::row_major> fa;
            wmma::fragment<wmma::matrix_b, 16, 16, 16, __half, wmma::row_major> fb;
            wmma::load_matrix_sync(fa, &smA[16 * wr * A_LD + kk * 16], A_LD);
            wmma::load_matrix_sync(fb, &smB[kk * 16 * FILTv + wc * 16], FILTv);
            wmma::mma_sync(acc, fa, fb, acc);
        }
        wmma::store_matrix_sync(&smC[16 * wr * FILTv + wc * 16], acc, FILTv, wmma::mem_row_major);
    }
    __syncthreads();

    // scatter to out: rows tr = n*8+m_local
    for (int i = t; i < 64 * FILTv; i += 256) {
        int rr = i >> 5, filt = i & 31;
        int nn = rr >> 3, ml = rr & 7;
        out[((size_t)nn * Mv + m0 + ml) * FILTv + filt] = smC[i];
    }
}

extern "C" void kernel_launch(void* const* d_in, const int* in_sizes, int n_in,
                              void* d_out, int out_size) {
    const float* x    = (const float*)d_in[0];
    const float* vals = (const float*)d_in[1];
    const float* kern = (const float*)d_in[2];
    const float* bias = (const float*)d_in[3];
    const int*   rows = (const int*)  d_in[4];
    const int*   cols = (const int*)  d_in[5];
    float* out = (float*)d_out;

    k_hist        <<<Ev / 256, 256>>>(rows);                     // 1
    k_scan        <<<1, 1024>>>();                               // 2
    k_scatter_init<<<1024 + Mv / 8, 256>>>(rows, cols, vals, x); // 3
    k_step<<<Mv / 8, 256>>>(0, 0, 1, 1);   // 4  T1 = L T0   <- profiled slot
    k_step<<<Mv / 8, 256>>>(1, 0, 2, 0);   // 5  T2
    k_step<<<Mv / 8, 256>>>(2, 1, 3, 0);   // 6  T3
    k_step_fin<<<Mv / 8, 256>>>(kern, bias, out);  // 7  T4 + GEMM + out
}

// round 10
// speedup vs baseline: 1.6061x; 1.6061x over previous
#include <cuda_runtime.h>
#include <cuda_fp16.h>
#include <mma.h>

using namespace nvcuda;

#define Mv    32768
#define Ev    262144
#define RANKv 5
#define FILTv 32
#define FINv  32
#define NBv   8
#define VEC   256   // FIN * NB

typedef unsigned long long u64;
typedef unsigned int u32;

struct alignas(8) Edge { int c; float w; };

// T terms fp16 (rank 4 never materialized), element layout per vertex: idx = n*32 + f
__device__ __half g_T[4][(size_t)Mv * VEC];
__device__ int    g_cnt[Mv];         // zero at module load; re-zeroed by k_scan1 each replay
__device__ int    g_rowptr[Mv];      // block-local exclusive scans
__device__ int    g_bsum[32];        // per-1024-chunk totals
__device__ int    g_pos[Ev];
__device__ Edge   g_edge[Ev];
__device__ __half g_W[160 * FILTv];  // W fp16, rows = kr*32+f

// warp-wide exclusive scan of g_bsum; returns base offset for chunk j (j uniform or per-lane)
__device__ __forceinline__ int chunk_base(int l, int j) {
    int own = g_bsum[l];
    int v = own;
#pragma unroll
    for (int off = 1; off < 32; off <<= 1) {
        int u = __shfl_up_sync(0xffffffffu, v, off);
        if (l >= off) v += u;
    }
    int excl = v - own;
    return __shfl_sync(0xffffffffu, excl, j & 31);
}

// ---------------- CSR build ----------------
__global__ void k_hist(const int* __restrict__ rows) {
    int e = blockIdx.x * 256 + threadIdx.x;
    g_pos[e] = atomicAdd(&g_cnt[rows[e]], 1);
}

// grid 33: blocks 0..31 scan 1024-element chunks of g_cnt (and re-zero);
// block 32 converts W to fp16 into g_W.
__global__ void k_scan1(const float* __restrict__ kern) {
    if (blockIdx.x == 32) {
        int t = threadIdx.x;
        for (int i = t; i < 160 * FILTv; i += 1024) {
            int row = i >> 5, filt = i & 31;
            int kr = row >> 5, f = row & 31;
            g_W[i] = __float2half_rn(kern[(f * RANKv + kr) * FILTv + filt]);
        }
        return;
    }
    __shared__ int sh[1024];
    int t = threadIdx.x;
    int i = blockIdx.x * 1024 + t;
    int c = g_cnt[i];
    g_cnt[i] = 0;
    sh[t] = c;
    __syncthreads();
#pragma unroll
    for (int off = 1; off < 1024; off <<= 1) {
        int v = (t >= off) ? sh[t - off] : 0;
        __syncthreads();
        sh[t] += v;
        __syncthreads();
    }
    g_rowptr[i] = sh[t] - c;                     // exclusive
    if (t == 1023) g_bsum[blockIdx.x] = sh[t];   // chunk total
}

// fused: blocks [0,1024) build edge array; blocks [1024,5120) transpose x -> T0 fp16
__global__ void __launch_bounds__(256) k_scatter_init(const int* __restrict__ rows,
                                                      const int* __restrict__ cols,
                                                      const float* __restrict__ vals,
                                                      const float* __restrict__ x) {
    int t = threadIdx.x;
    int l = t & 31;
    if (blockIdx.x < 1024) {
        int e = blockIdx.x * 256 + t;
        int r = rows[e];
        int base = chunk_base(l, r >> 10);       // per-lane j via shfl.idx
        int idx = base + g_rowptr[r] + g_pos[e];
        Edge ed; ed.c = cols[e] * VEC; ed.w = vals[e];
        g_edge[idx] = ed;
    } else {
        int b = blockIdx.x - 1024;
        int m = b * 8 + (t >> 5);
        int n = l >> 2;
        int f0 = 8 * (l & 3);
        const float* xp = &x[((size_t)n * Mv + m) * FINv + f0];
        float4 va = *(const float4*)xp;
        float4 vb = *(const float4*)(xp + 4);
        uint4 u;
        __half2 h;
        h = __floats2half2_rn(va.x, va.y); u.x = *(u32*)&h;
        h = __floats2half2_rn(va.z, va.w); u.y = *(u32*)&h;
        h = __floats2half2_rn(vb.x, vb.y); u.z = *(u32*)&h;
        h = __floats2half2_rn(vb.z, vb.w); u.w = *(u32*)&h;
        *(uint4*)&g_T[0][(size_t)m * VEC + 8 * l] = u;
    }
}

// row [start,end) bounds for row m, lane l
__device__ __forceinline__ void row_bounds(int m, int l, int& s, int& e) {
    int own = g_bsum[l];
    int v = own;
#pragma unroll
    for (int off = 1; off < 32; off <<= 1) {
        int u = __shfl_up_sync(0xffffffffu, v, off);
        if (l >= off) v += u;
    }
    int excl = v - own;
    s = __shfl_sync(0xffffffffu, excl, m >> 10) + g_rowptr[m];
    e = (m == Mv - 1) ? Ev
        : __shfl_sync(0xffffffffu, excl, ((m + 1) >> 10) & 31) + g_rowptr[m + 1];
}

// ---------------- Chebyshev step: one warp per row, fp16 in/out, fp32 accum ----------------
__global__ void __launch_bounds__(256) k_step(int prevIdx, int ppIdx, int curIdx, int isFirst) {
    int t = threadIdx.x;
    int w = t >> 5, l = t & 31;
    int m = blockIdx.x * 8 + w;

    const __half* __restrict__ Tprev = g_T[prevIdx];
    const __half* __restrict__ Tpp   = g_T[ppIdx];
    __half* __restrict__ Tcur        = g_T[curIdx];

    size_t base = (size_t)m * VEC + 8 * l;
    uint4 ppu = make_uint4(0, 0, 0, 0);
    if (!isFirst) ppu = *(const uint4*)&Tpp[base];

    int s, e;
    row_bounds(m, l, s, e);
    float2 a0 = {0.f,0.f}, a1 = {0.f,0.f}, a2 = {0.f,0.f}, a3 = {0.f,0.f};
    for (int i = s; i < e; i++) {
        Edge ed = g_edge[i];
        uint4 v = *(const uint4*)&Tprev[(size_t)ed.c + 8 * l];
        float wv = ed.w;
        float2 f0 = __half22float2(*(__half2*)&v.x);
        float2 f1 = __half22float2(*(__half2*)&v.y);
        float2 f2v = __half22float2(*(__half2*)&v.z);
        float2 f3 = __half22float2(*(__half2*)&v.w);
        a0.x += wv * f0.x;  a0.y += wv * f0.y;
        a1.x += wv * f1.x;  a1.y += wv * f1.y;
        a2.x += wv * f2v.x; a2.y += wv * f2v.y;
        a3.x += wv * f3.x;  a3.y += wv * f3.y;
    }

    if (!isFirst) {
        float2 p0 = __half22float2(*(__half2*)&ppu.x);
        float2 p1 = __half22float2(*(__half2*)&ppu.y);
        float2 p2 = __half22float2(*(__half2*)&ppu.z);
        float2 p3 = __half22float2(*(__half2*)&ppu.w);
        a0.x = 2.f * a0.x - p0.x;  a0.y = 2.f * a0.y - p0.y;
        a1.x = 2.f * a1.x - p1.x;  a1.y = 2.f * a1.y - p1.y;
        a2.x = 2.f * a2.x - p2.x;  a2.y = 2.f * a2.y - p2.y;
        a3.x = 2.f * a3.x - p3.x;  a3.y = 2.f * a3.y - p3.y;
    }

    uint4 u;
    __half2 h;
    h = __floats2half2_rn(a0.x, a0.y); u.x = *(u32*)&h;
    h = __floats2half2_rn(a1.x, a1.y); u.y = *(u32*)&h;
    h = __floats2half2_rn(a2.x, a2.y); u.z = *(u32*)&h;
    h = __floats2half2_rn(a3.x, a3.y); u.w = *(u32*)&h;
    *(uint4*)&Tcur[base] = u;
}

// ---------------- fused last step + tensor-core GEMM ----------------
#define A_LD 168   // 160 + 8 halfs pad

__global__ void __launch_bounds__(256) k_step_fin(const float* __restrict__ bias,
                                                  float* __restrict__ out) {
    __shared__ alignas(16) char smBuf[64 * A_LD * 2];     // smA (21504 B) / smC (8192 B) alias
    __shared__ alignas(16) __half smB[160 * FILTv];       // 10240 B
    __shared__ float smBias[16 * FILTv];                  //  2048 B
    __half* smA = (__half*)smBuf;
    float*  smC = (float*)smBuf;

    int t = threadIdx.x;
    int w = t >> 5, l = t & 31;
    int m0 = blockIdx.x * 8;
    int m = m0 + w;
    int n = l >> 2, f0 = 8 * (l & 3);
    int tr = n * 8 + w;

    // stage T0..T3 rows of A
#pragma unroll
    for (int kr = 0; kr < 4; kr++) {
        uint4 v = *(const uint4*)&g_T[kr][(size_t)m * VEC + 8 * l];
        *(uint4*)&smA[tr * A_LD + kr * 32 + f0] = v;
    }

    // B: bulk-copy pre-converted fp16 W
    for (int i = t; i < 640; i += 256)
        ((uint4*)smB)[i] = ((const uint4*)g_W)[i];
    for (int i = t; i < 16 * FILTv; i += 256)
        smBias[i] = bias[i & 31];

    // gather T4 = 2 L T3 - T2 for row m
    {
        const __half* __restrict__ Tprev = g_T[3];
        const __half* __restrict__ Tpp   = g_T[2];
        uint4 ppu = *(const uint4*)&Tpp[(size_t)m * VEC + 8 * l];

        int s, e;
        row_bounds(m, l, s, e);
        float2 a0 = {0.f,0.f}, a1 = {0.f,0.f}, a2 = {0.f,0.f}, a3 = {0.f,0.f};
        for (int i = s; i < e; i++) {
            Edge ed = g_edge[i];
            uint4 v = *(const uint4*)&Tprev[(size_t)ed.c + 8 * l];
            float wv = ed.w;
            float2 q0 = __half22float2(*(__half2*)&v.x);
            float2 q1 = __half22float2(*(__half2*)&v.y);
            float2 q2 = __half22float2(*(__half2*)&v.z);
            float2 q3 = __half22float2(*(__half2*)&v.w);
            a0.x += wv * q0.x; a0.y += wv * q0.y;
            a1.x += wv * q1.x; a1.y += wv * q1.y;
            a2.x += wv * q2.x; a2.y += wv * q2.y;
            a3.x += wv * q3.x; a3.y += wv * q3.y;
        }
        float2 p0 = __half22float2(*(__half2*)&ppu.x);
        float2 p1 = __half22float2(*(__half2*)&ppu.y);
        float2 p2 = __half22float2(*(__half2*)&ppu.z);
        float2 p3 = __half22float2(*(__half2*)&ppu.w);
        uint4 u;
        __half2 h;
        h = __floats2half2_rn(2.f*a0.x - p0.x, 2.f*a0.y - p0.y); u.x = *(u32*)&h;
        h = __floats2half2_rn(2.f*a1.x - p1.x, 2.f*a1.y - p1.y); u.y = *(u32*)&h;
        h = __floats2half2_rn(2.f*a2.x - p2.x, 2.f*a2.y - p2.y); u.z = *(u32*)&h;
        h = __floats2half2_rn(2.f*a3.x - p3.x, 2.f*a3.y - p3.y); u.w = *(u32*)&h;
        *(uint4*)&smA[tr * A_LD + 4 * 32 + f0] = u;
    }
    __syncthreads();

    // wmma: 8 warps -> 8 tiles (row-tile w>>1, col-tile w&1), acc init = bias
    {
        int wr = w >> 1, wc = w & 1;
        wmma::fragment<wmma::accumulator, 16, 16, 16, float> acc;
        wmma::load_matrix_sync(acc, smBias + wc * 16, FILTv, wmma::mem_row_major);
#pragma unroll
        for (int kk = 0; kk < 10; kk++) {
            wmma::fragment<wmma::matrix_a, 16, 16, 16, __half, wmma::row_major> fa;
            wmma::fragment<wmma::matrix_b, 16, 16, 16, __half, wmma::row_major> fb;
            wmma::load_matrix_sync(fa, &smA[16 * wr * A_LD + kk * 16], A_LD);
            wmma::load_matrix_sync(fb, &smB[kk * 16 * FILTv + wc * 16], FILTv);
            wmma::mma_sync(acc, fa, fb, acc);
        }
        __syncthreads();   // all smA reads done before smC overwrites the alias
        wmma::store_matrix_sync(&smC[16 * wr * FILTv + wc * 16], acc, FILTv, wmma::mem_row_major);
    }
    __syncthreads();

    // scatter to out: rows tr = n*8+m_local
    for (int i = t; i < 64 * FILTv; i += 256) {
        int rr = i >> 5, filt = i & 31;
        int nn = rr >> 3, ml = rr & 7;
        out[((size_t)nn * Mv + m0 + ml) * FILTv + filt] = smC[i];
    }
}

extern "C" void kernel_launch(void* const* d_in, const int* in_sizes, int n_in,
                              void* d_out, int out_size) {
    const float* x    = (const float*)d_in[0];
    const float* vals = (const float*)d_in[1];
    const float* kern = (const float*)d_in[2];
    const float* bias = (const float*)d_in[3];
    const int*   rows = (const int*)  d_in[4];
    const int*   cols = (const int*)  d_in[5];
    float* out = (float*)d_out;

    k_hist        <<<Ev / 256, 256>>>(rows);                     // 1
    k_scan1       <<<33, 1024>>>(kern);                          // 2 (parallel scan + W conv)
    k_scatter_init<<<1024 + Mv / 8, 256>>>(rows, cols, vals, x); // 3
    k_step<<<Mv / 8, 256>>>(0, 0, 1, 1);   // 4  T1 = L T0
    k_step<<<Mv / 8, 256>>>(1, 0, 2, 0);   // 5  T2
    k_step<<<Mv / 8, 256>>>(2, 1, 3, 0);   // 6  T3  <- profiled slot
    k_step_fin<<<Mv / 8, 256>>>(bias, out);  // 7  T4 + GEMM + out
}